// round 9
// baseline (speedup 1.0000x reference)
#include <cuda_runtime.h>
#include <math_constants.h>

#define BB 4
#define NN 512
#define HH 8
#define FF 16
#define DH 128
#define PN 8    // nodes per proj block
#define AW 16   // warps per attn block
#define LOG2E 1.44269504f

typedef unsigned long long u64;
#define ABSMASK2 0x7FFFFFFF7FFFFFFFull

__device__ __forceinline__ u64 addx2(u64 a, u64 b){ u64 d; asm("add.rn.f32x2 %0,%1,%2;" : "=l"(d) : "l"(a), "l"(b)); return d; }
__device__ __forceinline__ u64 mulx2(u64 a, u64 b){ u64 d; asm("mul.rn.f32x2 %0,%1,%2;" : "=l"(d) : "l"(a), "l"(b)); return d; }
__device__ __forceinline__ u64 fmax2(u64 a, u64 b, u64 c){ u64 d; asm("fma.rn.f32x2 %0,%1,%2,%3;" : "=l"(d) : "l"(a), "l"(b), "l"(c)); return d; }
__device__ __forceinline__ u64 pk2(float x, float y){ u64 r; asm("mov.b64 %0, {%1,%2};" : "=l"(r) : "r"(__float_as_uint(x)), "r"(__float_as_uint(y))); return r; }
__device__ __forceinline__ float2 unpk2(u64 v){ unsigned lo, hi; asm("mov.b64 {%0,%1}, %2;" : "=r"(lo), "=r"(hi) : "l"(v)); return make_float2(__uint_as_float(lo), __uint_as_float(hi)); }
__device__ __forceinline__ float ex2(float x){ float r; asm("ex2.approx.f32 %0,%1;" : "=f"(r) : "f"(x)); return r; }

// ---- scratch ----
__device__ float    d_h[2][BB*NN*DH];
__device__ float    d_gl[BB*NN*DH];          // SCALED: |0.4*log2e*a_f| * (h@Wl)
__device__ float    d_gr[BB*NN*DH];          // RAW:    h@Wr
__device__ float    d_dl[BB*NN*HH];          // log2e * 0.6 * (a . g_l_raw[n,h,:])
__device__ unsigned d_adjbits[BB*NN*(NN/32)];

// ---- tiny: zero the output (keeps ncu -s 5 on attn) ----
__global__ void zero_kernel(float* __restrict__ out)
{
    int i = blockIdx.x * 256 + threadIdx.x;
    if (i < BB*NN) out[i] = 0.f;
}

// ---- fused: h0 = X @ W_in, adj bit-packing ----
__global__ void prep_kernel(const float* __restrict__ x, const float* __restrict__ Win,
                            const int* __restrict__ adj)
{
    if (blockIdx.x < 1024) {
        int idx = blockIdx.x * 256 + threadIdx.x;
        int n = idx >> 7, d = idx & 127;
        d_h[0][idx] = fmaf(x[n*2], Win[d], x[n*2+1] * Win[DH + d]);
    } else {
        int gw   = ((blockIdx.x - 1024) * 256 + threadIdx.x) >> 5;
        int lane = threadIdx.x & 31;
        const int* row = adj + gw * NN;
        #pragma unroll
        for (int w = 0; w < NN/32; w++) {
            unsigned bits = __ballot_sync(0xffffffffu, row[w*32 + lane] != 0);
            if (lane == 0) d_adjbits[gw*(NN/32) + w] = bits;
        }
    }
}

// ---- projections: streaming double-buffered W, f32x2 node-pair math ----
// gl output is pre-scaled by |0.4*log2e*a_f| (sign handled in attn via LOP3).
__global__ void __launch_bounds__(256, 3) proj_kernel(const float* __restrict__ Wl,
                                                      const float* __restrict__ Wr,
                                                      const float* __restrict__ a, int src)
{
    __shared__ __align__(16) float sw[2][16][256];
    __shared__ __align__(16) u64   sph[DH][PN/2];

    int n0 = blockIdx.x * PN;
    int t  = threadIdx.x;

    {
        const float* h = d_h[src];
        #pragma unroll
        for (int r = 0; r < 2; r++) {
            int idx = r*256 + t;
            int k = idx >> 2, p = idx & 3;
            sph[k][p] = pk2(h[(n0 + 2*p)*DH + k], h[(n0 + 2*p + 1)*DH + k]);
        }
    }

    float4 rw[4];
    auto ldg_chunk = [&](int ck) {
        #pragma unroll
        for (int q = 0; q < 4; q++) {
            int idx = q*256 + t;
            int kk = idx >> 6, c4 = idx & 63;
            int k = ck*16 + kk;
            const float* s = (c4 < 32) ? (Wl + k*DH + c4*4) : (Wr + k*DH + (c4-32)*4);
            rw[q] = *(const float4*)s;
        }
    };
    auto sts_chunk = [&](int buf) {
        #pragma unroll
        for (int q = 0; q < 4; q++) {
            int idx = q*256 + t;
            int kk = idx >> 6, c4 = idx & 63;
            *(float4*)&sw[buf][kk][c4*4] = rw[q];
        }
    };

    ldg_chunk(0); sts_chunk(0);
    ldg_chunk(1);
    __syncthreads();

    int c = t;
    u64 acc2[PN/2];
    #pragma unroll
    for (int p = 0; p < PN/2; p++) acc2[p] = 0ull;

    #pragma unroll
    for (int ck = 0; ck < 8; ck++) {
        int buf = ck & 1;
        #pragma unroll
        for (int kk = 0; kk < 16; kk++) {
            float w = sw[buf][kk][c];
            u64 w2 = pk2(w, w);
            const ulonglong2* hp = (const ulonglong2*)&sph[ck*16 + kk][0];
            ulonglong2 h01 = hp[0], h23 = hp[1];
            acc2[0] = fmax2(h01.x, w2, acc2[0]);
            acc2[1] = fmax2(h01.y, w2, acc2[1]);
            acc2[2] = fmax2(h23.x, w2, acc2[2]);
            acc2[3] = fmax2(h23.y, w2, acc2[3]);
        }
        if (ck < 7) {
            sts_chunk((ck + 1) & 1);
            if (ck < 6) ldg_chunk(ck + 2);
            __syncthreads();
        }
    }

    int sel = c >> 7, d = c & 127;
    if (sel == 1) {
        // raw g_r
        #pragma unroll
        for (int p = 0; p < PN/2; p++) {
            float2 v = unpk2(acc2[p]);
            d_gr[(n0 + 2*p)*DH + d]     = v.x;
            d_gr[(n0 + 2*p + 1)*DH + d] = v.y;
        }
    } else {
        // dl from RAW acc, then store SCALED gl
        float av = 0.6f * LOG2E * a[d & 15];
        u64 av2 = pk2(av, av);
        u64 pr[PN/2];
        #pragma unroll
        for (int p = 0; p < PN/2; p++) pr[p] = mulx2(acc2[p], av2);
        #pragma unroll
        for (int off = 8; off; off >>= 1) {
            #pragma unroll
            for (int p = 0; p < PN/2; p++)
                pr[p] = addx2(pr[p], __shfl_down_sync(0xffffffffu, pr[p], off, 16));
        }
        if ((d & 15) == 0) {
            int hh = d >> 4;
            #pragma unroll
            for (int p = 0; p < PN/2; p++) {
                float2 v = unpk2(pr[p]);
                d_dl[(n0 + 2*p)*HH + hh]     = v.x;
                d_dl[(n0 + 2*p + 1)*HH + hh] = v.y;
            }
        }
        float mf = fabsf(0.4f * LOG2E * a[d & 15]);
        u64 mf2 = pk2(mf, mf);
        #pragma unroll
        for (int p = 0; p < PN/2; p++) {
            float2 v = unpk2(mulx2(acc2[p], mf2));
            d_gl[(n0 + 2*p)*DH + d]     = v.x;
            d_gl[(n0 + 2*p + 1)*DH + d] = v.y;
        }
    }
}

// ---- fused GATv2 attention: whole (b,h) slice smem-resident, sign-folded abs ----
// cf = 0.4*log2e*a_f; cf*|gri+glj| = sign(cf) * | |cf|gri + |cf|glj |.
// gl' (smem) and gri' (regs) pre-scaled by |cf|; abs+sign = ONE LOP3 per word:
//   u = (t & 0x7FFFFFFF) | signbit(cf).  e-accumulate is ADD2 (rt2, not FMA2 rt3).
__global__ void __launch_bounds__(512) attn_kernel(const float* __restrict__ a,
                                                   const float* __restrict__ Wout,
                                                   float* __restrict__ out,
                                                   int src, int last)
{
    __shared__ __align__(16) u64 s_pool[NN*16];            // 64KB
    __shared__ float s_dl[NN];                             // 2KB
    __shared__ float s_l[AW][32];

    int blk   = blockIdx.x;
    int itile = blk & 7;                      // N/64 = 8
    int hh    = (blk >> 3) & 7;
    int b     = blk >> 6;
    int wq    = threadIdx.x >> 5;             // 0..15, owns j in [wq*32, wq*32+32)
    int lane  = threadIdx.x & 31;
    int t     = threadIdx.x;
    int i0    = itile * 64 + lane;
    int ni0   = b * NN + i0;
    int ni1   = ni0 + 32;

    // ---- one-time cooperative slice load: gl' (scaled) + gr (raw) ----
    {
        const float* glb = d_gl + (b*NN*HH + hh)*FF;
        const float* grb = d_gr + (b*NN*HH + hh)*FF;
        #pragma unroll
        for (int r = 0; r < 8; r++) {
            int idx = r*512 + t;              // 0..4095
            int j = idx >> 3, s = idx & 7;
            const float4* srcp = (s < 4) ? ((const float4*)(glb + j*(HH*FF)) + s)
                                         : ((const float4*)(grb + j*(HH*FF)) + (s-4));
            *(float4*)&s_pool[j*16 + s*2] = *srcp;
        }
        s_dl[t] = d_dl[(b*NN + t)*HH + hh];
    }

    // sign bits and |cf| scaling for the two query rows
    u64 sb2[FF/2];
    u64 gri2a[FF/2], gri2b[FF/2];
    {
        const ulonglong2* gpa = (const ulonglong2*)(d_gr + (ni0*HH + hh)*FF);
        const ulonglong2* gpb = (const ulonglong2*)(d_gr + (ni1*HH + hh)*FF);
        #pragma unroll
        for (int q = 0; q < FF/2; q++) {
            float c0 = 0.4f * LOG2E * a[2*q];
            float c1 = 0.4f * LOG2E * a[2*q+1];
            sb2[q] = (u64)(__float_as_uint(c0) & 0x80000000u)
                   | ((u64)(__float_as_uint(c1) & 0x80000000u) << 32);
            u64 m2 = pk2(fabsf(c0), fabsf(c1));
            const u64* ga = (const u64*)gpa;
            const u64* gb = (const u64*)gpb;
            gri2a[q] = mulx2(ga[q], m2);
            gri2b[q] = mulx2(gb[q], m2);
        }
    }

    unsigned mba = d_adjbits[ni0*(NN/32) + wq];
    unsigned mbb = d_adjbits[ni1*(NN/32) + wq];

    __syncthreads();                               // slice resident

    float la0 = 0.f, la1 = 0.f, lb0 = 0.f, lb1 = 0.f;
    u64 acc2a[FF/2], acc2b[FF/2];
    #pragma unroll
    for (int q = 0; q < FF/2; q++) { acc2a[q] = 0ull; acc2b[q] = 0ull; }

    int jbase = wq * 32;
    #pragma unroll 4
    for (int jj = 0; jj < 32; jj++) {
        const ulonglong2* g2 = (const ulonglong2*)&s_pool[(jbase + jj)*16];
        u64 s0a = 0ull, s1a = 0ull, s0b = 0ull, s1b = 0ull;
        #pragma unroll
        for (int q = 0; q < 4; q++) {
            ulonglong2 gv = g2[q];
            u64 t0a = addx2(gri2a[2*q],   gv.x);
            u64 t1a = addx2(gri2a[2*q+1], gv.y);
            s0a = addx2(s0a, (t0a & ABSMASK2) | sb2[2*q]);
            s1a = addx2(s1a, (t1a & ABSMASK2) | sb2[2*q+1]);
            u64 t0b = addx2(gri2b[2*q],   gv.x);
            u64 t1b = addx2(gri2b[2*q+1], gv.y);
            s0b = addx2(s0b, (t0b & ABSMASK2) | sb2[2*q]);
            s1b = addx2(s1b, (t1b & ABSMASK2) | sb2[2*q+1]);
        }
        float2 sva = unpk2(addx2(s0a, s1a));
        float2 svb = unpk2(addx2(s0b, s1b));
        float dl = s_dl[jbase + jj];
        float pa = ((mba >> jj) & 1u) ? ex2((sva.x + sva.y) + dl) : 0.f;
        float pb = ((mbb >> jj) & 1u) ? ex2((svb.x + svb.y) + dl) : 0.f;
        if (jj & 1) { la1 += pa; lb1 += pb; } else { la0 += pa; lb0 += pb; }
        u64 p2a = pk2(pa, pa), p2b = pk2(pb, pb);
        const ulonglong2* gr2 = g2 + 4;
        #pragma unroll
        for (int q = 0; q < 4; q++) {
            ulonglong2 gv = gr2[q];
            acc2a[2*q]   = fmax2(p2a, gv.x, acc2a[2*q]);
            acc2a[2*q+1] = fmax2(p2a, gv.y, acc2a[2*q+1]);
            acc2b[2*q]   = fmax2(p2b, gv.x, acc2b[2*q]);
            acc2b[2*q+1] = fmax2(p2b, gv.y, acc2b[2*q+1]);
        }
    }
    float la = la0 + la1, lb = lb0 + lb1;

    // ---- two-pass parallel merge (pool reused; warp q<8 owns component q) ----
    __syncthreads();                             // slice consumed
    s_l[wq][lane] = la;
    #pragma unroll
    for (int q = 0; q < FF/2; q++)
        s_pool[(wq*32 + lane)*9 + q] = acc2a[q];
    __syncthreads();

    if (wq < 8) {
        int q = wq;
        float L = 0.f;
        u64 o = 0ull;
        #pragma unroll
        for (int w = 0; w < AW; w++) {
            L += s_l[w][lane];
            o = addx2(o, s_pool[(w*32 + lane)*9 + q]);
        }
        float inv = 1.f / L;
        if (!last) {
            u64* ho = (u64*)(d_h[src ^ 1] + (ni0*HH + hh)*FF);
            ho[q] = mulx2(o, pk2(inv, inv));
        } else {
            const float* wo = Wout + hh*FF;
            float2 ov = unpk2(o);
            atomicAdd(&out[ni0], (ov.x * wo[2*q] + ov.y * wo[2*q+1]) * inv);
        }
    }
    __syncthreads();                             // merge-A reads done

    s_l[wq][lane] = lb;
    #pragma unroll
    for (int q = 0; q < FF/2; q++)
        s_pool[(wq*32 + lane)*9 + q] = acc2b[q];
    __syncthreads();

    if (wq < 8) {
        int q = wq;
        float L = 0.f;
        u64 o = 0ull;
        #pragma unroll
        for (int w = 0; w < AW; w++) {
            L += s_l[w][lane];
            o = addx2(o, s_pool[(w*32 + lane)*9 + q]);
        }
        float inv = 1.f / L;
        if (!last) {
            u64* ho = (u64*)(d_h[src ^ 1] + (ni1*HH + hh)*FF);
            ho[q] = mulx2(o, pk2(inv, inv));
        } else {
            const float* wo = Wout + hh*FF;
            float2 ov = unpk2(o);
            atomicAdd(&out[ni1], (ov.x * wo[2*q] + ov.y * wo[2*q+1]) * inv);
        }
    }
}

extern "C" void kernel_launch(void* const* d_in, const int* in_sizes, int n_in,
                              void* d_out, int out_size)
{
    const float* nf   = (const float*)d_in[0];
    const int*   adj  = (const int*)  d_in[1];
    const float* Win  = (const float*)d_in[2];
    const float* Wl   = (const float*)d_in[3];
    const float* Wr   = (const float*)d_in[4];
    const float* aa   = (const float*)d_in[5];
    const float* Wout = (const float*)d_in[6];
    float* out = (float*)d_out;
    (void)in_sizes; (void)n_in; (void)out_size;

    zero_kernel<<<8, 256>>>(out);
    prep_kernel<<<1024 + 256, 256>>>(nf, Win, adj);
    for (int L = 0; L < 3; L++) {
        int src = L & 1;
        proj_kernel<<<(BB*NN)/PN, 256>>>(Wl + L*DH*DH, Wr + L*DH*DH, aa + L*FF, src);
        attn_kernel<<<BB*HH*(NN/64), 512>>>(aa + L*FF, Wout, out, src, L == 2);
    }
}

// round 10
// speedup vs baseline: 1.1788x; 1.1788x over previous
#include <cuda_runtime.h>
#include <math_constants.h>

#define BB 4
#define NN 512
#define HH 8
#define FF 16
#define DH 128
#define PN 8    // nodes per proj block
#define LOG2E 1.44269504f

typedef unsigned long long u64;
#define ABSMASK2 0x7FFFFFFF7FFFFFFFull
#define JST 18                       // u64 stride per j row in smem (144B, 16B aligned)
#define ATTN_SMEM (NN*JST*8)         // 73728 bytes

typedef unsigned uint_t;

__device__ __forceinline__ u64 addx2(u64 a, u64 b){ u64 d; asm("add.rn.f32x2 %0,%1,%2;" : "=l"(d) : "l"(a), "l"(b)); return d; }
__device__ __forceinline__ u64 mulx2(u64 a, u64 b){ u64 d; asm("mul.rn.f32x2 %0,%1,%2;" : "=l"(d) : "l"(a), "l"(b)); return d; }
__device__ __forceinline__ u64 fmax2(u64 a, u64 b, u64 c){ u64 d; asm("fma.rn.f32x2 %0,%1,%2,%3;" : "=l"(d) : "l"(a), "l"(b), "l"(c)); return d; }
__device__ __forceinline__ u64 pk2(float x, float y){ u64 r; asm("mov.b64 %0, {%1,%2};" : "=l"(r) : "r"(__float_as_uint(x)), "r"(__float_as_uint(y))); return r; }
__device__ __forceinline__ float2 unpk2(u64 v){ unsigned lo, hi; asm("mov.b64 {%0,%1}, %2;" : "=r"(lo), "=r"(hi) : "l"(v)); return make_float2(__uint_as_float(lo), __uint_as_float(hi)); }
__device__ __forceinline__ float ex2(float x){ float r; asm("ex2.approx.f32 %0,%1;" : "=f"(r) : "f"(x)); return r; }
__device__ __forceinline__ unsigned cvt_tf32(float x){ unsigned r; asm("cvt.rna.tf32.f32 %0, %1;" : "=r"(r) : "f"(x)); return r; }

__device__ __forceinline__ void mma_tf32(float& d0, float& d1, float& d2, float& d3,
                                         unsigned a0, unsigned a1, unsigned a2, unsigned a3,
                                         unsigned b0, unsigned b1)
{
    asm volatile(
        "mma.sync.aligned.m16n8k8.row.col.f32.tf32.tf32.f32 "
        "{%0,%1,%2,%3}, {%4,%5,%6,%7}, {%8,%9}, {%0,%1,%2,%3};\n"
        : "+f"(d0), "+f"(d1), "+f"(d2), "+f"(d3)
        : "r"(a0), "r"(a1), "r"(a2), "r"(a3), "r"(b0), "r"(b1));
}

// ---- scratch ----
__device__ float    d_h[2][BB*NN*DH];
__device__ float    d_gl[BB*NN*DH];          // raw h@Wl
__device__ float    d_gr[BB*NN*DH];          // raw h@Wr
__device__ float    d_dl[BB*NN*HH];          // log2e * 0.6 * (a . g_l[n,h,:])
__device__ unsigned d_adjbits[BB*NN*(NN/32)];

// ---- tiny: zero the output (keeps ncu -s 5 on attn) ----
__global__ void zero_kernel(float* __restrict__ out)
{
    int i = blockIdx.x * 256 + threadIdx.x;
    if (i < BB*NN) out[i] = 0.f;
}

// ---- fused: h0 = X @ W_in, adj bit-packing ----
__global__ void prep_kernel(const float* __restrict__ x, const float* __restrict__ Win,
                            const int* __restrict__ adj)
{
    if (blockIdx.x < 1024) {
        int idx = blockIdx.x * 256 + threadIdx.x;
        int n = idx >> 7, d = idx & 127;
        d_h[0][idx] = fmaf(x[n*2], Win[d], x[n*2+1] * Win[DH + d]);
    } else {
        int gw   = ((blockIdx.x - 1024) * 256 + threadIdx.x) >> 5;
        int lane = threadIdx.x & 31;
        const int* row = adj + gw * NN;
        #pragma unroll
        for (int w = 0; w < NN/32; w++) {
            unsigned bits = __ballot_sync(0xffffffffu, row[w*32 + lane] != 0);
            if (lane == 0) d_adjbits[gw*(NN/32) + w] = bits;
        }
    }
}

// ---- projections: streaming double-buffered W, f32x2 node-pair math (R7 version) ----
__global__ void __launch_bounds__(256, 3) proj_kernel(const float* __restrict__ Wl,
                                                      const float* __restrict__ Wr,
                                                      const float* __restrict__ a, int src)
{
    __shared__ __align__(16) float sw[2][16][256];
    __shared__ __align__(16) u64   sph[DH][PN/2];

    int n0 = blockIdx.x * PN;
    int t  = threadIdx.x;

    {
        const float* h = d_h[src];
        #pragma unroll
        for (int r = 0; r < 2; r++) {
            int idx = r*256 + t;
            int k = idx >> 2, p = idx & 3;
            sph[k][p] = pk2(h[(n0 + 2*p)*DH + k], h[(n0 + 2*p + 1)*DH + k]);
        }
    }

    float4 rw[4];
    auto ldg_chunk = [&](int ck) {
        #pragma unroll
        for (int q = 0; q < 4; q++) {
            int idx = q*256 + t;
            int kk = idx >> 6, c4 = idx & 63;
            int k = ck*16 + kk;
            const float* s = (c4 < 32) ? (Wl + k*DH + c4*4) : (Wr + k*DH + (c4-32)*4);
            rw[q] = *(const float4*)s;
        }
    };
    auto sts_chunk = [&](int buf) {
        #pragma unroll
        for (int q = 0; q < 4; q++) {
            int idx = q*256 + t;
            int kk = idx >> 6, c4 = idx & 63;
            *(float4*)&sw[buf][kk][c4*4] = rw[q];
        }
    };

    ldg_chunk(0); sts_chunk(0);
    ldg_chunk(1);
    __syncthreads();

    int c = t;
    u64 acc2[PN/2];
    #pragma unroll
    for (int p = 0; p < PN/2; p++) acc2[p] = 0ull;

    #pragma unroll
    for (int ck = 0; ck < 8; ck++) {
        int buf = ck & 1;
        #pragma unroll
        for (int kk = 0; kk < 16; kk++) {
            float w = sw[buf][kk][c];
            u64 w2 = pk2(w, w);
            const ulonglong2* hp = (const ulonglong2*)&sph[ck*16 + kk][0];
            ulonglong2 h01 = hp[0], h23 = hp[1];
            acc2[0] = fmax2(h01.x, w2, acc2[0]);
            acc2[1] = fmax2(h01.y, w2, acc2[1]);
            acc2[2] = fmax2(h23.x, w2, acc2[2]);
            acc2[3] = fmax2(h23.y, w2, acc2[3]);
        }
        if (ck < 7) {
            sts_chunk((ck + 1) & 1);
            if (ck < 6) ldg_chunk(ck + 2);
            __syncthreads();
        }
    }

    int sel = c >> 7, d = c & 127;
    float* g = sel ? d_gr : d_gl;
    #pragma unroll
    for (int p = 0; p < PN/2; p++) {
        float2 v = unpk2(acc2[p]);
        g[(n0 + 2*p)*DH + d]     = v.x;
        g[(n0 + 2*p + 1)*DH + d] = v.y;
    }
    if (sel == 0) {
        float av = 0.6f * LOG2E * a[d & 15];
        u64 av2 = pk2(av, av);
        u64 pr[PN/2];
        #pragma unroll
        for (int p = 0; p < PN/2; p++) pr[p] = mulx2(acc2[p], av2);
        #pragma unroll
        for (int off = 8; off; off >>= 1) {
            #pragma unroll
            for (int p = 0; p < PN/2; p++)
                pr[p] = addx2(pr[p], __shfl_down_sync(0xffffffffu, pr[p], off, 16));
        }
        if ((d & 15) == 0) {
            int hh = d >> 4;
            #pragma unroll
            for (int p = 0; p < PN/2; p++) {
                float2 v = unpk2(pr[p]);
                d_dl[(n0 + 2*p)*HH + hh]     = v.x;
                d_dl[(n0 + 2*p + 1)*HH + hh] = v.y;
            }
        }
    }
}

// p(e) for one (row, j): e = sum_f ar_f*|gri_f + glj_f| + dl;  p = bit ? 2^e : 0
__device__ __forceinline__ float attn_p(const u64* gri, const u64* gj, const u64* ar2,
                                        float dl, unsigned bit)
{
    u64 s0 = 0ull, s1 = 0ull;
    #pragma unroll
    for (int q = 0; q < 4; q++) {
        u64 t0 = addx2(gri[2*q],   gj[2*q])   & ABSMASK2;
        u64 t1 = addx2(gri[2*q+1], gj[2*q+1]) & ABSMASK2;
        s0 = fmax2(ar2[2*q],   t0, s0);
        s1 = fmax2(ar2[2*q+1], t1, s1);
    }
    float2 sv = unpk2(addx2(s0, s1));
    float pe = ex2((sv.x + sv.y) + dl);
    return bit ? pe : 0.f;
}

// ---- fused GATv2 attention: e-gen on FP32 pipes, PV-aggregation on tensor cores ----
// Block = (b, h, 64-i tile), 16 warps. Warp w: m-subtile = w&3 (16 i), j-range =
// (w>>2)*128. Lane: g = lane>>2 selects rows (g, g+8); t4 = lane&3 selects j cols.
// Per k8-tile the lane computes p for (r0,j0),(r1,j0),(r0,j1),(r1,j1) — exactly the
// m16n8k8 tf32 A-fragment — then 2 HMMA accumulate D[16i x 16f]. V pre-cvt to tf32.
__global__ void __launch_bounds__(512) attn_kernel(const float* __restrict__ a,
                                                   const float* __restrict__ Wout,
                                                   float* __restrict__ out,
                                                   int src, int last)
{
    extern __shared__ __align__(16) u64 s_pool[];   // [NN][JST]: gl 0..7, V(tf32) 8..15, dl @16

    int blk  = blockIdx.x;
    int it   = blk & 7;
    int hh   = (blk >> 3) & 7;
    int b    = blk >> 6;
    int t    = threadIdx.x;
    int w    = t >> 5;
    int lane = t & 31;
    int g    = lane >> 2;
    int t4   = lane & 3;
    int m    = w & 3;
    int js   = w >> 2;
    int jbase = js * 128;

    // ---- cooperative slice load: gl raw, gr converted to tf32 (V), dl ----
    {
        const float* glb = d_gl + (b*NN*HH + hh)*FF;
        const float* grb = d_gr + (b*NN*HH + hh)*FF;
        #pragma unroll
        for (int r = 0; r < 8; r++) {
            int idx = r*512 + t;                  // 0..4095
            int j = idx >> 3, s = idx & 7;
            if (s < 4) {
                float4 v = *((const float4*)(glb + j*(HH*FF)) + s);
                *(float4*)&s_pool[j*JST + s*2] = v;
            } else {
                float4 v = *((const float4*)(grb + j*(HH*FF)) + (s-4));
                uint4 cv;
                cv.x = cvt_tf32(v.x); cv.y = cvt_tf32(v.y);
                cv.z = cvt_tf32(v.z); cv.w = cvt_tf32(v.w);
                *(uint4*)&s_pool[j*JST + 8 + (s-4)*2] = cv;
            }
        }
        ((float*)&s_pool[t*JST + 16])[0] = d_dl[(b*NN + t)*HH + hh];
    }

    // rows owned by this lane
    int ni0 = b*NN + it*64 + m*16 + g;
    int ni1 = ni0 + 8;

    u64 gri0[8], gri1[8];
    {
        const u64* gp0 = (const u64*)(d_gr + (ni0*HH + hh)*FF);
        const u64* gp1 = (const u64*)(d_gr + (ni1*HH + hh)*FF);
        #pragma unroll
        for (int q = 0; q < 8; q++) { gri0[q] = gp0[q]; gri1[q] = gp1[q]; }
    }

    u64 ar2[8];
    #pragma unroll
    for (int q = 0; q < 8; q++)
        ar2[q] = pk2(0.4f * LOG2E * a[2*q], 0.4f * LOG2E * a[2*q+1]);

    unsigned mw0[4], mw1[4];
    #pragma unroll
    for (int k = 0; k < 4; k++) {
        mw0[k] = d_adjbits[ni0*(NN/32) + js*4 + k];
        mw1[k] = d_adjbits[ni1*(NN/32) + js*4 + k];
    }

    __syncthreads();                               // slice resident

    float d00 = 0.f, d01 = 0.f, d02 = 0.f, d03 = 0.f;   // n-tile 0 (f 0..7)
    float d10 = 0.f, d11 = 0.f, d12 = 0.f, d13 = 0.f;   // n-tile 1 (f 8..15)
    float l0 = 0.f, l1 = 0.f;

    for (int wt = 0; wt < 4; wt++) {               // mask word per 32 j
        unsigned mwa = mw0[wt], mwb = mw1[wt];
        #pragma unroll
        for (int k2 = 0; k2 < 4; k2++) {           // 4 k8-tiles per word
            int kt = wt*4 + k2;
            int j0 = jbase + kt*8 + t4;
            int j1 = j0 + 4;
            int bp = k2*8 + t4;
            const u64* gj0 = &s_pool[j0*JST];
            const u64* gj1 = &s_pool[j1*JST];

            u64 ga[8], gb[8];
            #pragma unroll
            for (int q = 0; q < 4; q++) {
                ulonglong2 v0 = ((const ulonglong2*)gj0)[q];
                ulonglong2 v1 = ((const ulonglong2*)gj1)[q];
                ga[2*q] = v0.x; ga[2*q+1] = v0.y;
                gb[2*q] = v1.x; gb[2*q+1] = v1.y;
            }
            float dl0 = ((const float*)(gj0 + 16))[0];
            float dl1 = ((const float*)(gj1 + 16))[0];

            float p00 = attn_p(gri0, ga, ar2, dl0, (mwa >> bp) & 1u);
            float p10 = attn_p(gri1, ga, ar2, dl0, (mwb >> bp) & 1u);
            float p01 = attn_p(gri0, gb, ar2, dl1, (mwa >> (bp+4)) & 1u);
            float p11 = attn_p(gri1, gb, ar2, dl1, (mwb >> (bp+4)) & 1u);
            l0 += p00 + p01;
            l1 += p10 + p11;

            unsigned a0 = cvt_tf32(p00), a1 = cvt_tf32(p10);
            unsigned a2 = cvt_tf32(p01), a3 = cvt_tf32(p11);

            const uint_t* v0 = (const uint_t*)(gj0 + 8);
            const uint_t* v1 = (const uint_t*)(gj1 + 8);
            mma_tf32(d00, d01, d02, d03, a0, a1, a2, a3, v0[g],   v1[g]);
            mma_tf32(d10, d11, d12, d13, a0, a1, a2, a3, v0[g+8], v1[g+8]);
        }
    }

    // ---- epilogue: stage D fragments + l, merge 4 j-split warps ----
    __syncthreads();                               // slice consumed; reuse pool
    float* stage = (float*)s_pool;                 // [256 rows][18]
    {
        int srow0 = (w*16 + g)*18, srow1 = (w*16 + g + 8)*18;
        *(float2*)&stage[srow0 + 2*t4]     = make_float2(d00, d01);
        *(float2*)&stage[srow0 + 8 + 2*t4] = make_float2(d10, d11);
        *(float2*)&stage[srow1 + 2*t4]     = make_float2(d02, d03);
        *(float2*)&stage[srow1 + 8 + 2*t4] = make_float2(d12, d13);
        l0 += __shfl_xor_sync(0xffffffffu, l0, 1);
        l0 += __shfl_xor_sync(0xffffffffu, l0, 2);
        l1 += __shfl_xor_sync(0xffffffffu, l1, 1);
        l1 += __shfl_xor_sync(0xffffffffu, l1, 2);
        if (t4 == 0) { stage[srow0 + 16] = l0; stage[srow1 + 16] = l1; }
    }
    __syncthreads();

    {
        int m2 = t >> 7, r = (t >> 3) & 15, fi = (t & 7) * 2;
        float s0 = 0.f, s1 = 0.f, L = 0.f;
        #pragma unroll
        for (int k = 0; k < 4; k++) {
            const float* row = &stage[((m2 + k*4)*16 + r)*18];
            s0 += row[fi];
            s1 += row[fi + 1];
            L  += row[16];
        }
        float inv = 1.f / L;
        int ni = b*NN + it*64 + m2*16 + r;
        if (!last) {
            *(float2*)(d_h[src ^ 1] + (ni*HH + hh)*FF + fi) = make_float2(s0*inv, s1*inv);
        } else {
            const float* wo = Wout + hh*FF;
            float part = s0*wo[fi] + s1*wo[fi+1];
            part += __shfl_down_sync(0xffffffffu, part, 1, 8);
            part += __shfl_down_sync(0xffffffffu, part, 2, 8);
            part += __shfl_down_sync(0xffffffffu, part, 4, 8);
            if ((t & 7) == 0) atomicAdd(&out[ni], part * inv);
        }
    }
}

extern "C" void kernel_launch(void* const* d_in, const int* in_sizes, int n_in,
                              void* d_out, int out_size)
{
    const float* nf   = (const float*)d_in[0];
    const int*   adj  = (const int*)  d_in[1];
    const float* Win  = (const float*)d_in[2];
    const float* Wl   = (const float*)d_in[3];
    const float* Wr   = (const float*)d_in[4];
    const float* aa   = (const float*)d_in[5];
    const float* Wout = (const float*)d_in[6];
    float* out = (float*)d_out;
    (void)in_sizes; (void)n_in; (void)out_size;

    static bool attr_set = false;
    if (!attr_set) {
        cudaFuncSetAttribute(attn_kernel, cudaFuncAttributeMaxDynamicSharedMemorySize,
                             ATTN_SMEM);
        attr_set = true;
    }

    zero_kernel<<<8, 256>>>(out);
    prep_kernel<<<1024 + 256, 256>>>(nf, Win, adj);
    for (int L = 0; L < 3; L++) {
        int src = L & 1;
        proj_kernel<<<(BB*NN)/PN, 256>>>(Wl + L*DH*DH, Wr + L*DH*DH, aa + L*FF, src);
        attn_kernel<<<BB*HH*(NN/64), 512, ATTN_SMEM>>>(aa + L*FF, Wout, out, src, L == 2);
    }
}

// round 11
// speedup vs baseline: 1.3526x; 1.1475x over previous
#include <cuda_runtime.h>
#include <math_constants.h>

#define BB 4
#define NN 512
#define HH 8
#define FF 16
#define DH 128
#define PN 8    // nodes per proj block
#define LOG2E 1.44269504f

typedef unsigned long long u64;
typedef unsigned uint_t;
#define ABSMASK2 0x7FFFFFFF7FFFFFFFull
#define JST 18                       // u64 stride per j row (144B: conflict-free, 16B aligned)
#define ATTN_SMEM (NN*JST*8)         // 73728 bytes -> 3 blocks/SM

__device__ __forceinline__ u64 addx2(u64 a, u64 b){ u64 d; asm("add.rn.f32x2 %0,%1,%2;" : "=l"(d) : "l"(a), "l"(b)); return d; }
__device__ __forceinline__ u64 mulx2(u64 a, u64 b){ u64 d; asm("mul.rn.f32x2 %0,%1,%2;" : "=l"(d) : "l"(a), "l"(b)); return d; }
__device__ __forceinline__ u64 fmax2(u64 a, u64 b, u64 c){ u64 d; asm("fma.rn.f32x2 %0,%1,%2,%3;" : "=l"(d) : "l"(a), "l"(b), "l"(c)); return d; }
__device__ __forceinline__ u64 pk2(float x, float y){ u64 r; asm("mov.b64 %0, {%1,%2};" : "=l"(r) : "r"(__float_as_uint(x)), "r"(__float_as_uint(y))); return r; }
__device__ __forceinline__ float2 unpk2(u64 v){ unsigned lo, hi; asm("mov.b64 {%0,%1}, %2;" : "=r"(lo), "=r"(hi) : "l"(v)); return make_float2(__uint_as_float(lo), __uint_as_float(hi)); }
__device__ __forceinline__ float ex2(float x){ float r; asm("ex2.approx.f32 %0,%1;" : "=f"(r) : "f"(x)); return r; }
__device__ __forceinline__ unsigned cvt_tf32(float x){ unsigned r; asm("cvt.rna.tf32.f32 %0, %1;" : "=r"(r) : "f"(x)); return r; }

__device__ __forceinline__ void mma_tf32(float& d0, float& d1, float& d2, float& d3,
                                         unsigned a0, unsigned a1, unsigned a2, unsigned a3,
                                         unsigned b0, unsigned b1)
{
    asm volatile(
        "mma.sync.aligned.m16n8k8.row.col.f32.tf32.tf32.f32 "
        "{%0,%1,%2,%3}, {%4,%5,%6,%7}, {%8,%9}, {%0,%1,%2,%3};\n"
        : "+f"(d0), "+f"(d1), "+f"(d2), "+f"(d3)
        : "r"(a0), "r"(a1), "r"(a2), "r"(a3), "r"(b0), "r"(b1));
}

// ---- scratch ----
__device__ float    d_h[2][BB*NN*DH];
__device__ float    d_gl[BB*NN*DH];          // raw h@Wl
__device__ float    d_gr[BB*NN*DH];          // raw h@Wr
__device__ float    d_dl[BB*NN*HH];          // log2e * 0.6 * (a . g_l[n,h,:])
__device__ unsigned d_adjbits[BB*NN*(NN/32)];

// ---- tiny: zero the output (keeps ncu -s 5 on attn) ----
__global__ void zero_kernel(float* __restrict__ out)
{
    int i = blockIdx.x * 256 + threadIdx.x;
    if (i < BB*NN) out[i] = 0.f;
}

// ---- fused: h0 = X @ W_in, adj bit-packing ----
__global__ void prep_kernel(const float* __restrict__ x, const float* __restrict__ Win,
                            const int* __restrict__ adj)
{
    if (blockIdx.x < 1024) {
        int idx = blockIdx.x * 256 + threadIdx.x;
        int n = idx >> 7, d = idx & 127;
        d_h[0][idx] = fmaf(x[n*2], Win[d], x[n*2+1] * Win[DH + d]);
    } else {
        int gw   = ((blockIdx.x - 1024) * 256 + threadIdx.x) >> 5;
        int lane = threadIdx.x & 31;
        const int* row = adj + gw * NN;
        #pragma unroll
        for (int w = 0; w < NN/32; w++) {
            unsigned bits = __ballot_sync(0xffffffffu, row[w*32 + lane] != 0);
            if (lane == 0) d_adjbits[gw*(NN/32) + w] = bits;
        }
    }
}

// ---- projections: streaming double-buffered W, f32x2 node-pair math ----
__global__ void __launch_bounds__(256, 3) proj_kernel(const float* __restrict__ Wl,
                                                      const float* __restrict__ Wr,
                                                      const float* __restrict__ a, int src)
{
    __shared__ __align__(16) float sw[2][16][256];
    __shared__ __align__(16) u64   sph[DH][PN/2];

    int n0 = blockIdx.x * PN;
    int t  = threadIdx.x;

    {
        const float* h = d_h[src];
        #pragma unroll
        for (int r = 0; r < 2; r++) {
            int idx = r*256 + t;
            int k = idx >> 2, p = idx & 3;
            sph[k][p] = pk2(h[(n0 + 2*p)*DH + k], h[(n0 + 2*p + 1)*DH + k]);
        }
    }

    float4 rw[4];
    auto ldg_chunk = [&](int ck) {
        #pragma unroll
        for (int q = 0; q < 4; q++) {
            int idx = q*256 + t;
            int kk = idx >> 6, c4 = idx & 63;
            int k = ck*16 + kk;
            const float* s = (c4 < 32) ? (Wl + k*DH + c4*4) : (Wr + k*DH + (c4-32)*4);
            rw[q] = *(const float4*)s;
        }
    };
    auto sts_chunk = [&](int buf) {
        #pragma unroll
        for (int q = 0; q < 4; q++) {
            int idx = q*256 + t;
            int kk = idx >> 6, c4 = idx & 63;
            *(float4*)&sw[buf][kk][c4*4] = rw[q];
        }
    };

    ldg_chunk(0); sts_chunk(0);
    ldg_chunk(1);
    __syncthreads();

    int c = t;
    u64 acc2[PN/2];
    #pragma unroll
    for (int p = 0; p < PN/2; p++) acc2[p] = 0ull;

    #pragma unroll
    for (int ck = 0; ck < 8; ck++) {
        int buf = ck & 1;
        #pragma unroll
        for (int kk = 0; kk < 16; kk++) {
            float w = sw[buf][kk][c];
            u64 w2 = pk2(w, w);
            const ulonglong2* hp = (const ulonglong2*)&sph[ck*16 + kk][0];
            ulonglong2 h01 = hp[0], h23 = hp[1];
            acc2[0] = fmax2(h01.x, w2, acc2[0]);
            acc2[1] = fmax2(h01.y, w2, acc2[1]);
            acc2[2] = fmax2(h23.x, w2, acc2[2]);
            acc2[3] = fmax2(h23.y, w2, acc2[3]);
        }
        if (ck < 7) {
            sts_chunk((ck + 1) & 1);
            if (ck < 6) ldg_chunk(ck + 2);
            __syncthreads();
        }
    }

    int sel = c >> 7, d = c & 127;
    float* g = sel ? d_gr : d_gl;
    #pragma unroll
    for (int p = 0; p < PN/2; p++) {
        float2 v = unpk2(acc2[p]);
        g[(n0 + 2*p)*DH + d]     = v.x;
        g[(n0 + 2*p + 1)*DH + d] = v.y;
    }
    if (sel == 0) {
        float av = 0.6f * LOG2E * a[d & 15];
        u64 av2 = pk2(av, av);
        u64 pr[PN/2];
        #pragma unroll
        for (int p = 0; p < PN/2; p++) pr[p] = mulx2(acc2[p], av2);
        #pragma unroll
        for (int off = 8; off; off >>= 1) {
            #pragma unroll
            for (int p = 0; p < PN/2; p++)
                pr[p] = addx2(pr[p], __shfl_down_sync(0xffffffffu, pr[p], off, 16));
        }
        if ((d & 15) == 0) {
            int hh = d >> 4;
            #pragma unroll
            for (int p = 0; p < PN/2; p++) {
                float2 v = unpk2(pr[p]);
                d_dl[(n0 + 2*p)*HH + hh]     = v.x;
                d_dl[(n0 + 2*p + 1)*HH + hh] = v.y;
            }
        }
    }
}

// p(e) for one (row, j): e = sum_f ar_f*|gri_f + glj_f| + dl;  p = bit ? 2^e : 0
__device__ __forceinline__ float attn_p(const u64* gri, const u64* gj, const u64* ar2,
                                        float dl, unsigned bit)
{
    u64 s0 = 0ull, s1 = 0ull;
    #pragma unroll
    for (int q = 0; q < 4; q++) {
        u64 t0 = addx2(gri[2*q],   gj[2*q])   & ABSMASK2;
        u64 t1 = addx2(gri[2*q+1], gj[2*q+1]) & ABSMASK2;
        s0 = fmax2(ar2[2*q],   t0, s0);
        s1 = fmax2(ar2[2*q+1], t1, s1);
    }
    float2 sv = unpk2(addx2(s0, s1));
    float pe = ex2((sv.x + sv.y) + dl);
    return bit ? pe : 0.f;
}

// ---- fused GATv2 attention: e-gen on FP32 pipes, PV-aggregation on tensor cores ----
// 256 thr / 8 warps, 3 blocks/SM. Warp w: m-subtile = w&3 (16 i), j-half = w>>2 (256 j).
// Lane: g = lane>>2 (rows g, g+8), t4 = lane&3 (j cols). Per k8-tile: lane computes the
// m16n8k8 tf32 A-fragment p's, then 2 HMMA into D[16i x 16f]. Both gri rows are re-read
// per tile from the smem slice via volatile LDS (reg diet -> 3 blocks/SM).
__global__ void __launch_bounds__(256, 3) attn_kernel(const float* __restrict__ a,
                                                      const float* __restrict__ Wout,
                                                      float* __restrict__ out,
                                                      int src, int last)
{
    extern __shared__ __align__(16) u64 s_pool[];   // [NN][JST]: gl 0..7, gr(f32) 8..15, dl @16

    int blk  = blockIdx.x;
    int it   = blk & 7;
    int hh   = (blk >> 3) & 7;
    int b    = blk >> 6;
    int t    = threadIdx.x;
    int w    = t >> 5;
    int lane = t & 31;
    int g    = lane >> 2;
    int t4   = lane & 3;
    int m    = w & 3;
    int js   = w >> 2;                    // 0..1, j in [js*256, js*256+256)

    // ---- cooperative slice load: gl raw + gr raw (exact f32), dl ----
    {
        const float* glb = d_gl + (b*NN*HH + hh)*FF;
        const float* grb = d_gr + (b*NN*HH + hh)*FF;
        #pragma unroll
        for (int r = 0; r < 16; r++) {
            int idx = r*256 + t;                  // 0..4095
            int j = idx >> 3, s = idx & 7;
            const float4* srcp = (s < 4) ? ((const float4*)(glb + j*(HH*FF)) + s)
                                         : ((const float4*)(grb + j*(HH*FF)) + (s-4));
            *(float4*)&s_pool[j*JST + s*2] = *srcp;
        }
        ((float*)&s_pool[t*JST + 16])[0]       = d_dl[(b*NN + t)*HH + hh];
        ((float*)&s_pool[(t+256)*JST + 16])[0] = d_dl[(b*NN + t + 256)*HH + hh];
    }

    int i_loc = it*64 + m*16 + g;
    int ni0 = b*NN + i_loc;
    int ni1 = ni0 + 8;

    u64 ar2[8];
    #pragma unroll
    for (int q = 0; q < 8; q++)
        ar2[q] = pk2(0.4f * LOG2E * a[2*q], 0.4f * LOG2E * a[2*q+1]);

    const unsigned* abr0 = d_adjbits + ni0*(NN/32) + js*8;
    const unsigned* abr1 = d_adjbits + ni1*(NN/32) + js*8;
    unsigned mwa = abr0[0], mwb = abr1[0];

    __syncthreads();                               // slice resident

    // volatile gri pointers into the slice's gr (f32) region — forces per-tile LDS
    const volatile u64* g0p = (const volatile u64*)&s_pool[(u64)i_loc*JST + 8];
    const volatile u64* g1p = (const volatile u64*)&s_pool[(u64)(i_loc + 8)*JST + 8];

    float d00 = 0.f, d01 = 0.f, d02 = 0.f, d03 = 0.f;   // n-tile 0 (f 0..7)
    float d10 = 0.f, d11 = 0.f, d12 = 0.f, d13 = 0.f;   // n-tile 1 (f 8..15)
    float l0 = 0.f, l1 = 0.f;

    for (int wt = 0; wt < 8; wt++) {               // 32 j per wt
        unsigned cmwa = mwa, cmwb = mwb;
        if (wt < 7) { mwa = abr0[wt+1]; mwb = abr1[wt+1]; }
        #pragma unroll
        for (int k2 = 0; k2 < 4; k2++) {
            int j0 = js*256 + wt*32 + k2*8 + t4;
            int j1 = j0 + 4;
            int bp = k2*8 + t4;
            const u64* gj0 = &s_pool[j0*JST];
            const u64* gj1 = &s_pool[j1*JST];

            u64 ga[8], gb[8];
            #pragma unroll
            for (int q = 0; q < 4; q++) {
                ulonglong2 v0 = ((const ulonglong2*)gj0)[q];
                ulonglong2 v1 = ((const ulonglong2*)gj1)[q];
                ga[2*q] = v0.x; ga[2*q+1] = v0.y;
                gb[2*q] = v1.x; gb[2*q+1] = v1.y;
            }
            u64 g0[8], g1[8];
            #pragma unroll
            for (int q = 0; q < 8; q++) { g0[q] = g0p[q]; g1[q] = g1p[q]; }

            float dl0 = ((const float*)(gj0 + 16))[0];
            float dl1 = ((const float*)(gj1 + 16))[0];

            float p00 = attn_p(g0, ga, ar2, dl0, (cmwa >> bp) & 1u);
            float p10 = attn_p(g1, ga, ar2, dl0, (cmwb >> bp) & 1u);
            float p01 = attn_p(g0, gb, ar2, dl1, (cmwa >> (bp+4)) & 1u);
            float p11 = attn_p(g1, gb, ar2, dl1, (cmwb >> (bp+4)) & 1u);
            l0 += p00 + p01;
            l1 += p10 + p11;

            unsigned a0 = cvt_tf32(p00), a1 = cvt_tf32(p10);
            unsigned a2 = cvt_tf32(p01), a3 = cvt_tf32(p11);

            const float* v0f = (const float*)(gj0 + 8);
            const float* v1f = (const float*)(gj1 + 8);
            unsigned bA0 = cvt_tf32(v0f[g]),   bA1 = cvt_tf32(v1f[g]);
            unsigned bB0 = cvt_tf32(v0f[g+8]), bB1 = cvt_tf32(v1f[g+8]);
            mma_tf32(d00, d01, d02, d03, a0, a1, a2, a3, bA0, bA1);
            mma_tf32(d10, d11, d12, d13, a0, a1, a2, a3, bB0, bB1);
        }
    }

    // ---- epilogue: stage D fragments + l, merge the 2 j-halves ----
    __syncthreads();                               // slice consumed; reuse pool
    float* stage = (float*)s_pool;                 // [128 rows][18]
    {
        int srow0 = (js*64 + m*16 + g)*18;
        int srow1 = srow0 + 8*18;
        *(float2*)&stage[srow0 + 2*t4]     = make_float2(d00, d01);
        *(float2*)&stage[srow0 + 8 + 2*t4] = make_float2(d10, d11);
        *(float2*)&stage[srow1 + 2*t4]     = make_float2(d02, d03);
        *(float2*)&stage[srow1 + 8 + 2*t4] = make_float2(d12, d13);
        l0 += __shfl_xor_sync(0xffffffffu, l0, 1);
        l0 += __shfl_xor_sync(0xffffffffu, l0, 2);
        l1 += __shfl_xor_sync(0xffffffffu, l1, 1);
        l1 += __shfl_xor_sync(0xffffffffu, l1, 2);
        if (t4 == 0) { stage[srow0 + 16] = l0; stage[srow1 + 16] = l1; }
    }
    __syncthreads();

    {
        int r = t & 63, fq = t >> 6;               // row in tile, f-quad
        const float* r0 = &stage[r*18];
        const float* r1 = &stage[(64 + r)*18];
        float s0 = r0[fq*4+0] + r1[fq*4+0];
        float s1 = r0[fq*4+1] + r1[fq*4+1];
        float s2 = r0[fq*4+2] + r1[fq*4+2];
        float s3 = r0[fq*4+3] + r1[fq*4+3];
        float L  = r0[16] + r1[16];
        float inv = 1.f / L;
        int ni = b*NN + it*64 + r;
        if (!last) {
            *(float4*)(d_h[src ^ 1] + (ni*HH + hh)*FF + fq*4) =
                make_float4(s0*inv, s1*inv, s2*inv, s3*inv);
        } else {
            const float* wo = Wout + hh*FF + fq*4;
            float part = s0*wo[0] + s1*wo[1] + s2*wo[2] + s3*wo[3];
            atomicAdd(&out[ni], part * inv);
        }
    }
}

extern "C" void kernel_launch(void* const* d_in, const int* in_sizes, int n_in,
                              void* d_out, int out_size)
{
    const float* nf   = (const float*)d_in[0];
    const int*   adj  = (const int*)  d_in[1];
    const float* Win  = (const float*)d_in[2];
    const float* Wl   = (const float*)d_in[3];
    const float* Wr   = (const float*)d_in[4];
    const float* aa   = (const float*)d_in[5];
    const float* Wout = (const float*)d_in[6];
    float* out = (float*)d_out;
    (void)in_sizes; (void)n_in; (void)out_size;

    static bool attr_set = false;
    if (!attr_set) {
        cudaFuncSetAttribute(attn_kernel, cudaFuncAttributeMaxDynamicSharedMemorySize,
                             ATTN_SMEM);
        attr_set = true;
    }

    zero_kernel<<<8, 256>>>(out);
    prep_kernel<<<1024 + 256, 256>>>(nf, Win, adj);
    for (int L = 0; L < 3; L++) {
        int src = L & 1;
        proj_kernel<<<(BB*NN)/PN, 256>>>(Wl + L*DH*DH, Wr + L*DH*DH, aa + L*FF, src);
        attn_kernel<<<BB*HH*(NN/64), 256, ATTN_SMEM>>>(aa + L*FF, Wout, out, src, L == 2);
    }
}